// round 14
// baseline (speedup 1.0000x reference)
#include <cuda_runtime.h>
#include <cuda_fp16.h>
#include <cuda_bf16.h>
#include <math.h>

#define MAXN 100352
#define MAXE 3276800

// ---------------- scratch (__device__ globals) -------------------------------
__device__ int     g_deg[MAXN];
__device__ int     g_rowStart[MAXN];
__device__ int     g_part[1024];
__device__ float   g_dinv[MAXN];
__device__ int     g_csr[MAXE];              // BYTE offsets: src * 128
__device__ int     g_erank[MAXE];            // per-edge rank within its dst
__device__ int     g_is64;
__device__ int     g_scanctr;
__device__ int     g_scanflag;
__device__ __half2 g_hbuf1[(size_t)MAXN * 32];   // X@W1 (prescaled after scatter_scale)
__device__ __half2 g_hbuf3[(size_t)MAXN * 32];   // h1s = dinv*relu(h1)  (fp16)
__device__ float   g_buf2[(size_t)MAXN * 64];    // u = agg2 result (fp32)

__device__ __forceinline__ int load_idx(const void* ei, size_t pos) {
    if (g_is64) return (int)((const long long*)ei)[pos];
    return ((const int*)ei)[pos];
}

// ---------------- fused: zero counters + dtype detect + flag reset -----------
__global__ void k_zero_detect(const int* __restrict__ ei32, int N, int nPairs) {
    int i = blockIdx.x * blockDim.x + threadIdx.x;
    if (i < N) g_deg[i] = 0;
    if (i == 0) { g_scanctr = 0; g_scanflag = 0; }
    if (blockIdx.x == 0) {
        __shared__ int sh[256];
        int t = threadIdx.x;
        int acc = 0;
        for (int p = t; p < nPairs; p += 256) acc |= ei32[2 * p + 1];
        sh[t] = acc; __syncthreads();
        for (int off = 128; off > 0; off >>= 1) {
            if (t < off) sh[t] |= sh[t + off];
            __syncthreads();
        }
        if (t == 0) g_is64 = (sh[0] == 0) ? 1 : 0;
    }
}

// ---------------- tensor-core GEMM body (bf16 split, 3-term) -----------------
__device__ __forceinline__ void mma16816(float c[4], unsigned a0, unsigned a1,
                                         unsigned a2, unsigned a3,
                                         unsigned b0, unsigned b1) {
    asm volatile(
        "mma.sync.aligned.m16n8k16.row.col.f32.bf16.bf16.f32 "
        "{%0,%1,%2,%3}, {%4,%5,%6,%7}, {%8,%9}, {%0,%1,%2,%3};"
        : "+f"(c[0]), "+f"(c[1]), "+f"(c[2]), "+f"(c[3])
        : "r"(a0), "r"(a1), "r"(a2), "r"(a3), "r"(b0), "r"(b1));
}

#define KC 32

struct GemmSmem {
    __nv_bfloat16 As_h[128][KC + 2];
    __nv_bfloat16 As_l[128][KC + 2];
    __nv_bfloat16 Wt_h[64][KC + 2];
    __nv_bfloat16 Wt_l[64][KC + 2];
};

// If Cf != nullptr: fp32 epilogue Cf[row*64+col] = c + bias[col].
// Else: fp16 epilogue to Ch (unscaled).
__device__ void gemm_body(GemmSmem& s, const float* __restrict__ A,
                          const float* __restrict__ W, __half2* __restrict__ Ch,
                          float* __restrict__ Cf, const float* __restrict__ bias,
                          int M, int K, int blk) {
    int tid  = threadIdx.x;
    int warp = tid >> 5, lane = tid & 31;
    int g    = lane >> 2, tg = lane & 3;
    int m0   = blk * 128;
    int mrow = warp * 16;

    float c[8][4];
#pragma unroll
    for (int t = 0; t < 8; t++)
#pragma unroll
        for (int j = 0; j < 4; j++) c[t][j] = 0.0f;

    int nC = K / KC;
    for (int ch = 0; ch < nC; ch++) {
        int k0 = ch * KC;
#pragma unroll
        for (int i = 0; i < 4; i++) {
            int idx = tid + i * 256;
            int row = idx >> 3, c4 = (idx & 7) * 4;
            float4 v = make_float4(0.f, 0.f, 0.f, 0.f);
            int gr = m0 + row;
            if (gr < M) v = *(const float4*)(A + (size_t)gr * K + k0 + c4);
            float vv[4] = {v.x, v.y, v.z, v.w};
#pragma unroll
            for (int q = 0; q < 4; q++) {
                __nv_bfloat16 hi = __float2bfloat16(vv[q]);
                __nv_bfloat16 lo = __float2bfloat16(vv[q] - __bfloat162float(hi));
                s.As_h[row][c4 + q] = hi;
                s.As_l[row][c4 + q] = lo;
            }
        }
#pragma unroll
        for (int i = 0; i < 8; i++) {
            int idx = tid + i * 256;
            int k = idx >> 6, n = idx & 63;
            float v = W[(size_t)(k0 + k) * 64 + n];
            __nv_bfloat16 hi = __float2bfloat16(v);
            __nv_bfloat16 lo = __float2bfloat16(v - __bfloat162float(hi));
            s.Wt_h[n][k] = hi;
            s.Wt_l[n][k] = lo;
        }
        __syncthreads();

#pragma unroll
        for (int ks = 0; ks < 2; ks++) {
            int kb = ks * 16;
            unsigned ah0 = *(const unsigned*)&s.As_h[mrow + g][kb + tg * 2];
            unsigned ah1 = *(const unsigned*)&s.As_h[mrow + g + 8][kb + tg * 2];
            unsigned ah2 = *(const unsigned*)&s.As_h[mrow + g][kb + tg * 2 + 8];
            unsigned ah3 = *(const unsigned*)&s.As_h[mrow + g + 8][kb + tg * 2 + 8];
            unsigned al0 = *(const unsigned*)&s.As_l[mrow + g][kb + tg * 2];
            unsigned al1 = *(const unsigned*)&s.As_l[mrow + g + 8][kb + tg * 2];
            unsigned al2 = *(const unsigned*)&s.As_l[mrow + g][kb + tg * 2 + 8];
            unsigned al3 = *(const unsigned*)&s.As_l[mrow + g + 8][kb + tg * 2 + 8];
#pragma unroll
            for (int t = 0; t < 8; t++) {
                unsigned bh0 = *(const unsigned*)&s.Wt_h[t * 8 + g][kb + tg * 2];
                unsigned bh1 = *(const unsigned*)&s.Wt_h[t * 8 + g][kb + tg * 2 + 8];
                unsigned bl0 = *(const unsigned*)&s.Wt_l[t * 8 + g][kb + tg * 2];
                unsigned bl1 = *(const unsigned*)&s.Wt_l[t * 8 + g][kb + tg * 2 + 8];
                mma16816(c[t], ah0, ah1, ah2, ah3, bh0, bh1);
                mma16816(c[t], ah0, ah1, ah2, ah3, bl0, bl1);
                mma16816(c[t], al0, al1, al2, al3, bh0, bh1);
            }
        }
        __syncthreads();
    }

    int r0 = m0 + mrow + g;
    int r1 = r0 + 8;
    if (Cf != nullptr) {
#pragma unroll
        for (int t = 0; t < 8; t++) {
            int col = t * 8 + tg * 2;
            float b0 = bias[col], b1 = bias[col + 1];
            if (r0 < M) {
                Cf[(size_t)r0 * 64 + col]     = c[t][0] + b0;
                Cf[(size_t)r0 * 64 + col + 1] = c[t][1] + b1;
            }
            if (r1 < M) {
                Cf[(size_t)r1 * 64 + col]     = c[t][2] + b0;
                Cf[(size_t)r1 * 64 + col + 1] = c[t][3] + b1;
            }
        }
    } else {
#pragma unroll
        for (int t = 0; t < 8; t++) {
            int col2 = (t * 8 + tg * 2) >> 1;
            if (r0 < M) Ch[(size_t)r0 * 32 + col2] = __floats2half2_rn(c[t][0], c[t][1]);
            if (r1 < M) Ch[(size_t)r1 * 32 + col2] = __floats2half2_rn(c[t][2], c[t][3]);
        }
    }
}

// ---------------- fused: GEMM1 blocks + hist blocks (hist emits edge rank) ---
__global__ void __launch_bounds__(256) k_gemm1_hist(const float* __restrict__ A,
                                                    const float* __restrict__ W,
                                                    int M, int K,
                                                    const void* __restrict__ ei, int E,
                                                    int gemmBlocks) {
    __shared__ GemmSmem s;
    if ((int)blockIdx.x < gemmBlocks) {
        gemm_body(s, A, W, g_hbuf1, nullptr, nullptr, M, K, blockIdx.x);
    } else {
        int e = (blockIdx.x - gemmBlocks) * 256 + threadIdx.x;
        if (e < E) {
            int d = load_idx(ei, (size_t)E + e);
            g_erank[e] = atomicAdd(&g_deg[d], 1);
        }
    }
}

// ---------------- GEMM2: u @ W2 + b2 -> fp32 out -----------------------------
__global__ void __launch_bounds__(256) k_gemm_out(const float* __restrict__ W,
                                                  const float* __restrict__ bias,
                                                  float* __restrict__ out,
                                                  int M, int K) {
    __shared__ GemmSmem s;
    gemm_body(s, (const float*)g_buf2, W, nullptr, out, bias, M, K, blockIdx.x);
}

// ---------------- single-kernel scan (spin-flag, all blocks resident) --------
__global__ void __launch_bounds__(256) k_scanall(int N, int nb) {
    __shared__ int sh[256];
    __shared__ int shT[256];
    int b = blockIdx.x, t = threadIdx.x, i = b * 256 + t;
    int v = (i < N) ? g_deg[i] : 0;

    sh[t] = v; __syncthreads();
    for (int off = 1; off < 256; off <<= 1) {
        int x = (t >= off) ? sh[t - off] : 0;
        __syncthreads();
        sh[t] += x;
        __syncthreads();
    }
    if (t == 255) g_part[b] = sh[255];
    __threadfence();
    __syncthreads();
    if (t == 0) atomicAdd(&g_scanctr, 1);

    if (b == 0) {
        if (t == 0) { while (*(volatile int*)&g_scanctr < nb) {} }
        __syncthreads();
        int t4 = t * 4;
        int a0 = (t4 + 0 < nb) ? g_part[t4 + 0] : 0;
        int a1 = (t4 + 1 < nb) ? g_part[t4 + 1] : 0;
        int a2 = (t4 + 2 < nb) ? g_part[t4 + 2] : 0;
        int a3 = (t4 + 3 < nb) ? g_part[t4 + 3] : 0;
        int s0 = a0, s1 = s0 + a1, s2 = s1 + a2, s3 = s2 + a3;
        shT[t] = s3; __syncthreads();
        for (int off = 1; off < 256; off <<= 1) {
            int x = (t >= off) ? shT[t - off] : 0;
            __syncthreads();
            shT[t] += x;
            __syncthreads();
        }
        int base = shT[t] - s3;
        if (t4 + 0 < nb) g_part[t4 + 0] = base;
        if (t4 + 1 < nb) g_part[t4 + 1] = base + s0;
        if (t4 + 2 < nb) g_part[t4 + 2] = base + s1;
        if (t4 + 3 < nb) g_part[t4 + 3] = base + s2;
        __threadfence();
        __syncthreads();
        if (t == 0) atomicExch(&g_scanflag, 1);
    }

    if (t == 0) { while (*(volatile int*)&g_scanflag == 0) {} }
    __syncthreads();

    if (i < N) {
        g_rowStart[i] = g_part[b] + sh[t] - v;
        g_dinv[i] = rsqrtf((float)(v + 1));
    }
}

// ---------------- fused: atomic-free scatter + prescale-hbuf1 ----------------
// csr entry = src * 128 (byte offset of the fp16 row).
__global__ void k_scatter_scale(const void* __restrict__ ei, int E, int N,
                                int scatBlocks) {
    if ((int)blockIdx.x < scatBlocks) {
        int e = blockIdx.x * 256 + threadIdx.x;
        if (e < E) {
            int s = load_idx(ei, (size_t)e);
            int d = load_idx(ei, (size_t)E + e);
            g_csr[g_rowStart[d] + g_erank[e]] = s << 7;   // byte offset, no atomic
        }
    } else {
        int idx = (blockIdx.x - scatBlocks) * 256 + threadIdx.x;
        if (idx < N * 32) {
            int row = idx >> 5;
            float2 v = __half22float2(g_hbuf1[idx]);
            float d = g_dinv[row];
            g_hbuf1[idx] = __floats2half2_rn(v.x * d, v.y * d);
        }
    }
}

// ---------------- aggregation: quarter-warp per edge, LDG.128 gathers --------
// Quarter q (lanes 8q..8q+7) handles edge j+q; lane (q,sub) reads bytes
// [16*sub, 16*sub+16) of the 128B fp16 row = channels 8*sub .. 8*sub+7.
// Pairs of rows combined with HADD2 (same rounding as previous scheme), then
// fp32. Cross-quarter reduce via shfl_xor(8,16) at the end.
// mode 0 (layer1): in=g_hbuf1; h1=relu(dinv*acc+b1); store fp16(dinv*h1)->g_hbuf3.
// mode 1 (layer2): in=g_hbuf3; u=dinv*acc; store fp32 u -> g_buf2.
__global__ void k_agg(const float* __restrict__ bias, int N, int mode) {
    const __half2* hs = (mode == 0) ? (const __half2*)g_hbuf1
                                    : (const __half2*)g_hbuf3;

    int gw = (blockIdx.x * blockDim.x + threadIdx.x) >> 5;
    int lane = threadIdx.x & 31;
    if (gw >= N) return;

    int q   = lane >> 3;
    int sub = lane & 7;
    const char* lanep = (const char*)hs + sub * 16;

    int beg = g_rowStart[gw];
    int dg  = g_deg[gw];

    // self-loop: only quarter 0 seeds its accumulators with the node's own row
    float2 accf[4];
    {
        uint4 sv = *(const uint4*)(lanep + (size_t)gw * 128);
        float2 f0 = __half22float2(*(__half2*)&sv.x);
        float2 f1 = __half22float2(*(__half2*)&sv.y);
        float2 f2 = __half22float2(*(__half2*)&sv.z);
        float2 f3 = __half22float2(*(__half2*)&sv.w);
        float z = (q == 0) ? 1.f : 0.f;
        accf[0] = make_float2(f0.x * z, f0.y * z);
        accf[1] = make_float2(f1.x * z, f1.y * z);
        accf[2] = make_float2(f2.x * z, f2.y * z);
        accf[3] = make_float2(f3.x * z, f3.y * z);
    }

    int e = beg, end = beg + dg;
    while (e < end) {
        int rem = end - e;
        int off = 0;
        if (lane < rem) off = g_csr[e + lane];
        int cnt = rem < 32 ? rem : 32;
        int j = 0;
        // 8 edges per step: quarter q takes edges j+q and j+4+q
        for (; j + 8 <= cnt; j += 8) {
            int o0 = __shfl_sync(0xffffffffu, off, j + q);
            int o1 = __shfl_sync(0xffffffffu, off, j + 4 + q);
            uint4 a = *(const uint4*)(lanep + o0);
            uint4 b = *(const uint4*)(lanep + o1);
            __half2 h0 = __hadd2(*(__half2*)&a.x, *(__half2*)&b.x);
            __half2 h1 = __hadd2(*(__half2*)&a.y, *(__half2*)&b.y);
            __half2 h2 = __hadd2(*(__half2*)&a.z, *(__half2*)&b.z);
            __half2 h3 = __hadd2(*(__half2*)&a.w, *(__half2*)&b.w);
            float2 f0 = __half22float2(h0);
            float2 f1 = __half22float2(h1);
            float2 f2 = __half22float2(h2);
            float2 f3 = __half22float2(h3);
            accf[0].x += f0.x; accf[0].y += f0.y;
            accf[1].x += f1.x; accf[1].y += f1.y;
            accf[2].x += f2.x; accf[2].y += f2.y;
            accf[3].x += f3.x; accf[3].y += f3.y;
        }
        // 4-edge step
        if (j + 4 <= cnt) {
            int o = __shfl_sync(0xffffffffu, off, j + q);
            uint4 a = *(const uint4*)(lanep + o);
            float2 f0 = __half22float2(*(__half2*)&a.x);
            float2 f1 = __half22float2(*(__half2*)&a.y);
            float2 f2 = __half22float2(*(__half2*)&a.z);
            float2 f3 = __half22float2(*(__half2*)&a.w);
            accf[0].x += f0.x; accf[0].y += f0.y;
            accf[1].x += f1.x; accf[1].y += f1.y;
            accf[2].x += f2.x; accf[2].y += f2.y;
            accf[3].x += f3.x; accf[3].y += f3.y;
            j += 4;
        }
        // leftover (<4): all quarters read the edge; only quarter 0 accumulates
        for (; j < cnt; j++) {
            int o = __shfl_sync(0xffffffffu, off, j);
            uint4 a = *(const uint4*)(lanep + o);
            if (q == 0) {
                float2 f0 = __half22float2(*(__half2*)&a.x);
                float2 f1 = __half22float2(*(__half2*)&a.y);
                float2 f2 = __half22float2(*(__half2*)&a.z);
                float2 f3 = __half22float2(*(__half2*)&a.w);
                accf[0].x += f0.x; accf[0].y += f0.y;
                accf[1].x += f1.x; accf[1].y += f1.y;
                accf[2].x += f2.x; accf[2].y += f2.y;
                accf[3].x += f3.x; accf[3].y += f3.y;
            }
        }
        e += 32;
    }

    // cross-quarter reduction: lanes {sub, sub+8, sub+16, sub+24} hold the
    // same channels -> xor-reduce over bits 3 and 4 of lane id
#pragma unroll
    for (int k = 0; k < 4; k++) {
        accf[k].x += __shfl_xor_sync(0xffffffffu, accf[k].x, 8);
        accf[k].y += __shfl_xor_sync(0xffffffffu, accf[k].y, 8);
        accf[k].x += __shfl_xor_sync(0xffffffffu, accf[k].x, 16);
        accf[k].y += __shfl_xor_sync(0xffffffffu, accf[k].y, 16);
    }

    if (lane < 8) {   // sub == lane, q == 0: one writer per channel group
        float di = g_dinv[gw];
        if (mode == 0) {
            const float* bp = bias + 8 * sub;
            float v0 = fmaxf(di * accf[0].x + bp[0], 0.f);
            float v1 = fmaxf(di * accf[0].y + bp[1], 0.f);
            float v2 = fmaxf(di * accf[1].x + bp[2], 0.f);
            float v3 = fmaxf(di * accf[1].y + bp[3], 0.f);
            float v4 = fmaxf(di * accf[2].x + bp[4], 0.f);
            float v5 = fmaxf(di * accf[2].y + bp[5], 0.f);
            float v6 = fmaxf(di * accf[3].x + bp[6], 0.f);
            float v7 = fmaxf(di * accf[3].y + bp[7], 0.f);
            uint4 pk;
            *(__half2*)&pk.x = __floats2half2_rn(di * v0, di * v1);
            *(__half2*)&pk.y = __floats2half2_rn(di * v2, di * v3);
            *(__half2*)&pk.z = __floats2half2_rn(di * v4, di * v5);
            *(__half2*)&pk.w = __floats2half2_rn(di * v6, di * v7);
            *(uint4*)((char*)g_hbuf3 + (size_t)gw * 128 + sub * 16) = pk;
        } else {
            float* op = (float*)g_buf2 + (size_t)gw * 64 + 8 * sub;
            *(float4*)op = make_float4(di * accf[0].x, di * accf[0].y,
                                       di * accf[1].x, di * accf[1].y);
            *(float4*)(op + 4) = make_float4(di * accf[2].x, di * accf[2].y,
                                             di * accf[3].x, di * accf[3].y);
        }
    }
}

// ---------------- launch -----------------------------------------------------
extern "C" void kernel_launch(void* const* d_in, const int* in_sizes, int n_in,
                              void* d_out, int out_size) {
    const float* x  = (const float*)d_in[0];
    const void*  ei = d_in[1];
    const float* W1 = (const float*)d_in[2];
    const float* b1 = (const float*)d_in[3];
    const float* W2 = (const float*)d_in[4];
    const float* b2 = (const float*)d_in[5];
    float* out = (float*)d_out;

    int N = in_sizes[0] / 256;
    int E = in_sizes[1] / 2;

    int nb = (N + 255) / 256;
    int eb = (E + 255) / 256;
    int gemm_blocks  = (N + 127) / 128;
    int agg_blocks   = (N + 7) / 8;
    int scale_blocks = (N * 32 + 255) / 256;
    int nPairs = (E < 2048) ? E : 2048;

    k_zero_detect<<<nb, 256>>>((const int*)ei, N, nPairs);               // 1
    k_gemm1_hist<<<gemm_blocks + eb, 256>>>(x, W1, N, 256, ei, E,
                                            gemm_blocks);                // 2
    k_scanall<<<nb, 256>>>(N, nb);                                       // 3
    k_scatter_scale<<<eb + scale_blocks, 256>>>(ei, E, N, eb);           // 4 <- profiled
    k_agg<<<agg_blocks, 256>>>(b1, N, 0);                                // 5
    k_agg<<<agg_blocks, 256>>>(b2, N, 1);                                // 6
    k_gemm_out<<<gemm_blocks, 256>>>(W2, b2, out, N, 64);                // 7
}